// round 17
// baseline (speedup 1.0000x reference)
#include <cuda_runtime.h>

// R14 structure (best: 245.0us) with ONE delta: cb2 pin removed — ONLY cb3
// carries L2::evict_last. R16 showed extra pins (cb1) cost bandwidth by
// crowding the streaming traffic out of L2 ways; cb1/cb2 are small enough to
// stay resident on recency alone. cb4 remains nc.L2::evict_first (the one
// policy with a proven win); pts=__ldcs, out=__stcs.
// 8 lanes/pt; lane g = lane&7 owns corner (dx,dy,dz)=(g&1,(g>>1)&1,g>>2);
// one LDG.256 per lane per level; butterfly reduce-distribute -> lane g = feat g.

// HINT: 0 = plain nc, 1 = L2::evict_last (cb3 only), 2 = L2::evict_first (cb4)
template<int HINT>
__device__ __forceinline__ void ld_corner256(const float* __restrict__ p, float* v)
{
    unsigned r0, r1, r2, r3, r4, r5, r6, r7;
    if (HINT == 1) {
        asm("ld.global.nc.L2::evict_last.v8.b32 {%0,%1,%2,%3,%4,%5,%6,%7}, [%8];"
            : "=r"(r0), "=r"(r1), "=r"(r2), "=r"(r3),
              "=r"(r4), "=r"(r5), "=r"(r6), "=r"(r7) : "l"(p));
    } else if (HINT == 2) {
        asm("ld.global.nc.L2::evict_first.v8.b32 {%0,%1,%2,%3,%4,%5,%6,%7}, [%8];"
            : "=r"(r0), "=r"(r1), "=r"(r2), "=r"(r3),
              "=r"(r4), "=r"(r5), "=r"(r6), "=r"(r7) : "l"(p));
    } else {
        asm("ld.global.nc.v8.b32 {%0,%1,%2,%3,%4,%5,%6,%7}, [%8];"
            : "=r"(r0), "=r"(r1), "=r"(r2), "=r"(r3),
              "=r"(r4), "=r"(r5), "=r"(r6), "=r"(r7) : "l"(p));
    }
    v[0] = __uint_as_float(r0); v[1] = __uint_as_float(r1);
    v[2] = __uint_as_float(r2); v[3] = __uint_as_float(r3);
    v[4] = __uint_as_float(r4); v[5] = __uint_as_float(r5);
    v[6] = __uint_as_float(r6); v[7] = __uint_as_float(r7);
}

template<int RES, int HINT>
__device__ __forceinline__ void lerp_add(const float* __restrict__ cb,
                                         float px, float py, float pz,
                                         int dx, int dy, int dz,
                                         float sx, float cx,
                                         float sy, float cy,
                                         float sz, float cz,
                                         float* acc)
{
    const float s = (float)(RES - 1);
    float x = px * s, y = py * s, z = pz * s;

    // pts in [0,1) -> coords >= 0 -> trunc == floor; clamp upper in int
    int x0 = min((int)x, RES - 2);
    int y0 = min((int)y, RES - 2);
    int z0 = min((int)z, RES - 2);

    // d ? f : 1-f == fma(s, f, c), s=+/-1, c=0/1 (hoisted per lane)
    float wx = fmaf(sx, x - (float)x0, cx);
    float wy = fmaf(sy, y - (float)y0, cy);
    float wz = fmaf(sz, z - (float)z0, cz);
    float w  = wx * wy * wz;

    int idx = (x0 + dx) + (y0 + dy) * RES + (z0 + dz) * (RES * RES);
    const float* p = cb + (size_t)idx * 8;

    float v[8];
    ld_corner256<HINT>(p, v);

    #pragma unroll
    for (int i = 0; i < 8; ++i)
        acc[i] = fmaf(w, v[i], acc[i]);
}

__device__ __forceinline__ float reduce_distribute(float* acc, int g)
{
    float t[4];
    {
        bool k = (g & 1);
        #pragma unroll
        for (int j = 0; j < 4; ++j) {
            float snd = k ? acc[2 * j] : acc[2 * j + 1];
            float rcv = __shfl_xor_sync(0xffffffffu, snd, 1);
            float kep = k ? acc[2 * j + 1] : acc[2 * j];
            t[j] = kep + rcv;
        }
    }
    float u[2];
    {
        bool k = (g >> 1) & 1;
        #pragma unroll
        for (int j = 0; j < 2; ++j) {
            float snd = k ? t[2 * j] : t[2 * j + 1];
            float rcv = __shfl_xor_sync(0xffffffffu, snd, 2);
            float kep = k ? t[2 * j + 1] : t[2 * j];
            u[j] = kep + rcv;
        }
    }
    {
        bool k = (g >> 2) & 1;
        float snd = k ? u[0] : u[1];
        float rcv = __shfl_xor_sync(0xffffffffu, snd, 4);
        float kep = k ? u[1] : u[0];
        return kep + rcv;
    }
}

__global__ void __launch_bounds__(256, 7) dense_grid_8lane_kernel(
    const float* __restrict__ pts,
    const float* __restrict__ cb0,
    const float* __restrict__ cb1,
    const float* __restrict__ cb2,
    const float* __restrict__ cb3,
    const float* __restrict__ cb4,
    float* __restrict__ out,
    int n)
{
    int tid  = blockIdx.x * blockDim.x + threadIdx.x;
    int lane = threadIdx.x & 31;
    int g    = lane & 7;                      // corner id within 8-lane group
    int pt   = (tid >> 5) * 4 + (lane >> 3);  // 4 points per warp

    bool valid = (pt < n);
    int ptc = valid ? pt : (n - 1);

    // read-once stream
    float px = __ldcs(&pts[3 * ptc + 0]);
    float py = __ldcs(&pts[3 * ptc + 1]);
    float pz = __ldcs(&pts[3 * ptc + 2]);

    int dx = g & 1, dy = (g >> 1) & 1, dz = g >> 2;

    float sx = dx ? 1.0f : -1.0f, cx = dx ? 0.0f : 1.0f;
    float sy = dy ? 1.0f : -1.0f, cy = dy ? 0.0f : 1.0f;
    float sz = dz ? 1.0f : -1.0f, cz = dz ? 0.0f : 1.0f;

    float acc[8];
    #pragma unroll
    for (int i = 0; i < 8; ++i) acc[i] = 0.0f;

    lerp_add< 16, 0>(cb0, px, py, pz, dx, dy, dz, sx, cx, sy, cy, sz, cz, acc);
    lerp_add< 32, 0>(cb1, px, py, pz, dx, dy, dz, sx, cx, sy, cy, sz, cz, acc);
    lerp_add< 64, 0>(cb2, px, py, pz, dx, dy, dz, sx, cx, sy, cy, sz, cz, acc);
    lerp_add<128, 1>(cb3, px, py, pz, dx, dy, dz, sx, cx, sy, cy, sz, cz, acc);  // pin (only)
    lerp_add<256, 2>(cb4, px, py, pz, dx, dy, dz, sx, cx, sy, cy, sz, cz, acc);  // stream

    float r = reduce_distribute(acc, g);

    if (valid) {
        // write-once stream
        __stcs(&out[(size_t)pt * 8 + g], r);
    }
}

extern "C" void kernel_launch(void* const* d_in, const int* in_sizes, int n_in,
                              void* d_out, int out_size)
{
    const float* pts = (const float*)d_in[0];
    const float* cb0 = (const float*)d_in[1];
    const float* cb1 = (const float*)d_in[2];
    const float* cb2 = (const float*)d_in[3];
    const float* cb3 = (const float*)d_in[4];
    const float* cb4 = (const float*)d_in[5];
    float* out = (float*)d_out;

    int n = in_sizes[0] / 3;                 // pts is [N,3]
    int total_threads = ((n + 3) / 4) * 32;  // 8 lanes/pt, 4 pts/warp
    int threads = 256;
    int blocks = (total_threads + threads - 1) / threads;
    dense_grid_8lane_kernel<<<blocks, threads>>>(pts, cb0, cb1, cb2, cb3, cb4, out, n);
}